// round 17
// baseline (speedup 1.0000x reference)
#include <cuda_runtime.h>
#include <cstdint>

#define BB 16
#define NN 577
#define HH 12
#define NT 512
#define XS 2304          // x row stride (floats)
#define OS 768           // out row stride (floats)
#define SCALEF 0.125f
#define NCH 10           // 10 chunks x 64 keys = 640 >= 577

#define QS 68            // stride for Q/K/P hi-lo tiles (68 mod 32 = 4 -> conflict-free frags)
#define VS 136           // V' stride (136 mod 32 = 8 -> conflict-free B frags)

// ---- smem offsets (floats) ----
#define OFF_QHI 0        // [64][68]
#define OFF_QLO 4352
#define OFF_KHI 8704     // [64][68] per chunk
#define OFF_KLO 13056
#define OFF_VHI 17408    // [64][136] per chunk: cols 0..63 V, 64..87 Iv, 88..111 Ih, 112 p0, 113 ones, 114..135 pad
#define OFF_VLO 26112
#define OFF_PHI 34816    // [64][68] p hi
#define OFF_PLO 39168    // [64][68] p lo
#define OFF_BV  43520    // [64][24]
#define OFF_BH  45056    // [64][24]
#define OFF_B0  46592    // [64]
#define SMEM_FLOATS 46656   // 186,624 B

#define OFF_QF   OFF_PHI    // fp32 Q scratch (A-phase only)
#define OFF_TK   OFF_PLO    // rel_k tables   (A-phase only)
#define OFF_PART OFF_KHI    // O' staging [64][128] (after chunk loop)

__device__ __forceinline__ int clip14(int v) {
    v = v < -14 ? -14 : (v > 14 ? 14 : v);
    return v + 15;
}
__device__ __forceinline__ uint32_t cvt_tf32(float f) {
    uint32_t r; asm("cvt.rna.tf32.f32 %0, %1;" : "=r"(r) : "f"(f)); return r;
}
__device__ __forceinline__ void split2(float f, float& hi, float& lo) {
    hi = __uint_as_float(cvt_tf32(f));
    lo = __uint_as_float(cvt_tf32(f - hi));
}
__device__ __forceinline__ void mma_tf32(float* c, uint32_t a0, uint32_t a1, uint32_t a2,
                                         uint32_t a3, uint32_t b0, uint32_t b1) {
    asm volatile(
        "mma.sync.aligned.m16n8k8.row.col.f32.tf32.tf32.f32 "
        "{%0,%1,%2,%3},{%4,%5,%6,%7},{%8,%9},{%0,%1,%2,%3};"
        : "+f"(c[0]), "+f"(c[1]), "+f"(c[2]), "+f"(c[3])
        : "r"(a0), "r"(a1), "r"(a2), "r"(a3), "r"(b0), "r"(b1));
}
#define DOT4(A, Q, K) { A += Q.x*K.x; A += Q.y*K.y; A += Q.z*K.z; A += Q.w*K.w; }

__global__ __launch_bounds__(NT, 1)
void attn_kernel(const float* __restrict__ x, const float* __restrict__ wts,
                 const float* __restrict__ tkv, const float* __restrict__ tkh,
                 const float* __restrict__ tvv, const float* __restrict__ tvh,
                 float* __restrict__ out)
{
    extern __shared__ float sm[];
    const int tid = threadIdx.x;
    const int wid = tid >> 5, lane = tid & 31;
    const int ly = lane >> 2, lx = lane & 3;
    const int rowblk = wid & 3, colblk = wid >> 2;
    const int R0 = rowblk * 16;
    const int qt = blockIdx.x, h = blockIdx.y, b = blockIdx.z;
    const int n0 = qt * 64;

    float w = __ldg(&wts[2]);
    if (h < 10) w += __ldg(&wts[1]);
    if (h < 8)  w += __ldg(&wts[0]);

    // ---------------- A1: Q -> fp32 scratch + hi/lo; rel_k tables; zero V' indicator region
    for (int idx = tid; idx < 64 * 16; idx += NT) {
        int n = idx >> 4, d4 = idx & 15;
        int qn = n0 + n;
        float4 f = make_float4(0.f, 0.f, 0.f, 0.f);
        if (qn < NN)
            f = *(const float4*)&x[((size_t)(b * NN + qn)) * XS + h * 64 + d4 * 4];
        float4 q = make_float4(f.x * w, f.y * w, f.z * w, f.w * w);
        *(float4*)&sm[OFF_QF + n * QS + d4 * 4] = q;
        float4 hi, lo;
        split2(q.x, hi.x, lo.x); split2(q.y, hi.y, lo.y);
        split2(q.z, hi.z, lo.z); split2(q.w, hi.w, lo.w);
        *(float4*)&sm[OFF_QHI + n * QS + d4 * 4] = hi;
        *(float4*)&sm[OFF_QLO + n * QS + d4 * 4] = lo;
    }
    for (int idx = tid; idx < 960; idx += NT) {
        int which = (idx >= 480) ? 1 : 0;
        int i2 = idx - which * 480;
        int t = i2 >> 4, d4 = i2 & 15;
        const float* src = which ? tkh : tkv;
        float4 f = *(const float4*)&src[t * 64 + d4 * 4];
        *(float4*)&sm[OFF_TK + which * 30 * QS + t * QS + d4 * 4] = f;
    }
    for (int idx = tid; idx < 2304; idx += NT) {   // zero V' cols 64..135, both hi & lo
        int a = (idx >= 1152) ? 1 : 0;
        int i2 = idx - a * 1152;
        int mm = i2 / 18, j = i2 - mm * 18;
        *(float4*)&sm[(a ? OFF_VLO : OFF_VHI) + mm * VS + 64 + j * 4] =
            make_float4(0.f, 0.f, 0.f, 0.f);
    }
    __syncthreads();

    // ---------------- A2: rel-k bias coefficients (b0, bv[24], bh[24]) per query row
    {
        int n = tid >> 3, l = tid & 7;
        int qn = n0 + n;
        bool zi = (qn == 0) || (qn >= NN);
        int gq = 0, cq = 0;
        if (!zi) { gq = (qn - 1) / 24; cq = (qn - 1) % 24; }
        const float4* qrow = (const float4*)&sm[OFF_QF + n * QS];
        const float* skv = &sm[OFF_TK];
        const float* skh = &sm[OFF_TK + 30 * QS];
        for (int jj = l; jj < 49; jj += 8) {
            float s = 0.f;
            if (jj == 0) {
                const float4* t0p = (const float4*)skv;
                const float4* t1p = (const float4*)skh;
                #pragma unroll 4
                for (int d4 = 0; d4 < 16; d4++) {
                    float4 q = qrow[d4], a = t0p[d4], c2 = t1p[d4];
                    s += q.x*(a.x+c2.x) + q.y*(a.y+c2.y) + q.z*(a.z+c2.z) + q.w*(a.w+c2.w);
                }
                sm[OFF_B0 + n] = s;
            } else if (jj <= 24) {
                int g = jj - 1;
                int t = zi ? 0 : clip14(g - gq);
                const float4* tr = (const float4*)&skv[t * QS];
                #pragma unroll 4
                for (int d4 = 0; d4 < 16; d4++) { float4 q = qrow[d4], a = tr[d4]; DOT4(s, q, a); }
                sm[OFF_BV + n * 24 + g] = s;
            } else {
                int c2 = jj - 25;
                int t = zi ? 0 : clip14(c2 - cq);
                const float4* tr = (const float4*)&skh[t * QS];
                #pragma unroll 4
                for (int d4 = 0; d4 < 16; d4++) { float4 q = qrow[d4], a = tr[d4]; DOT4(s, q, a); }
                sm[OFF_BH + n * 24 + c2] = s;
            }
        }
    }

    // ---------------- fused chunk loop: QK-MMA -> exp -> PV'-MMA (O' accum in regs)
    float accO[4][4] = {{0,0,0,0},{0,0,0,0},{0,0,0,0},{0,0,0,0}};

    for (int c = 0; c < NCH; c++) {
        __syncthreads();   // prior PV reads (or A2 for c=0) complete before overwrites

        // K chunk -> hi/lo
        for (int idx = tid; idx < 64 * 16; idx += NT) {
            int mm = idx >> 4, d4 = idx & 15;
            int m = c * 64 + mm;
            float4 f = make_float4(0.f, 0.f, 0.f, 0.f);
            if (m < NN)
                f = *(const float4*)&x[((size_t)(b * NN + m)) * XS + 768 + h * 64 + d4 * 4];
            float4 k = make_float4(f.x * w, f.y * w, f.z * w, f.w * w);
            float4 hi, lo;
            split2(k.x, hi.x, lo.x); split2(k.y, hi.y, lo.y);
            split2(k.z, hi.z, lo.z); split2(k.w, hi.w, lo.w);
            *(float4*)&sm[OFF_KHI + mm * QS + d4 * 4] = hi;
            *(float4*)&sm[OFF_KLO + mm * QS + d4 * 4] = lo;
        }
        // V chunk cols 0..63 -> hi/lo
        for (int idx = tid; idx < 64 * 16; idx += NT) {
            int mm = idx >> 4, d4 = idx & 15;
            int m = c * 64 + mm;
            float4 f = make_float4(0.f, 0.f, 0.f, 0.f);
            if (m < NN)
                f = *(const float4*)&x[((size_t)(b * NN + m)) * XS + 1536 + h * 64 + d4 * 4];
            float4 v = make_float4(f.x * w, f.y * w, f.z * w, f.w * w);
            float4 hi, lo;
            split2(v.x, hi.x, lo.x); split2(v.y, hi.y, lo.y);
            split2(v.z, hi.z, lo.z); split2(v.w, hi.w, lo.w);
            *(float4*)&sm[OFF_VHI + mm * VS + d4 * 4] = hi;
            *(float4*)&sm[OFF_VLO + mm * VS + d4 * 4] = lo;
        }
        // indicator maintenance (one thread per key row; clear prev chunk's marks, set new)
        if (tid < 64) {
            int mm = tid;
            float* vr = &sm[OFF_VHI + mm * VS];
            if (c > 0) {
                int mp = (c - 1) * 64 + mm;
                if (mp < NN) {
                    if (mp >= 1) { vr[64 + (mp - 1) / 24] = 0.f; vr[88 + (mp - 1) % 24] = 0.f; }
                    else vr[112] = 0.f;
                    vr[113] = 0.f;
                }
            }
            int m = c * 64 + mm;
            if (m < NN) {
                if (m >= 1) { vr[64 + (m - 1) / 24] = 1.f; vr[88 + (m - 1) % 24] = 1.f; }
                else vr[112] = 1.f;
                vr[113] = 1.f;
            }
        }
        __syncthreads();

        // ---- QK: S-chunk = Q K^T (3-term tf32) ----
        float acc[2][4] = {{0,0,0,0},{0,0,0,0}};
        {
            const uint32_t* qh = (const uint32_t*)&sm[OFF_QHI + (R0 + ly) * QS + lx];
            const uint32_t* ql = (const uint32_t*)&sm[OFF_QLO + (R0 + ly) * QS + lx];
            #pragma unroll
            for (int k8 = 0; k8 < 8; k8++) {
                int kc = k8 * 8;
                uint32_t ah0 = qh[kc], ah1 = qh[8*QS + kc], ah2 = qh[kc+4], ah3 = qh[8*QS + kc+4];
                uint32_t al0 = ql[kc], al1 = ql[8*QS + kc], al2 = ql[kc+4], al3 = ql[8*QS + kc+4];
                #pragma unroll
                for (int nt = 0; nt < 2; nt++) {
                    int nb = colblk * 16 + nt * 8;
                    const uint32_t* bh = (const uint32_t*)&sm[OFF_KHI + (nb + ly) * QS + kc + lx];
                    const uint32_t* bl = (const uint32_t*)&sm[OFF_KLO + (nb + ly) * QS + kc + lx];
                    uint32_t bh0 = bh[0], bh1 = bh[4], bl0 = bl[0], bl1 = bl[4];
                    mma_tf32(acc[nt], ah0, ah1, ah2, ah3, bh0, bh1);
                    mma_tf32(acc[nt], al0, al1, al2, al3, bh0, bh1);
                    mma_tf32(acc[nt], ah0, ah1, ah2, ah3, bl0, bl1);
                }
            }
        }
        // ---- exp writeback -> p hi/lo ----
        #pragma unroll
        for (int nt = 0; nt < 2; nt++) {
            int mloc = colblk * 16 + nt * 8 + lx * 2;
            int m = c * 64 + mloc, m1 = m + 1;
            bool v0 = m < NN, v1 = m1 < NN;
            int gm  = (m  - 1) / 24, cm  = (m  - 1) - gm  * 24;
            int gm1 = (m1 - 1) / 24, cm1 = (m1 - 1) - gm1 * 24;
            #pragma unroll
            for (int half = 0; half < 2; half++) {
                int r = R0 + ly + half * 8;
                float p0 = 0.f, p1 = 0.f;
                if (v0) {
                    float bias = (m == 0) ? sm[OFF_B0 + r]
                               : sm[OFF_BV + r*24 + gm] + sm[OFF_BH + r*24 + cm];
                    p0 = __expf((acc[nt][half*2] + bias) * SCALEF);
                }
                if (v1) {
                    float bias = sm[OFF_BV + r*24 + gm1] + sm[OFF_BH + r*24 + cm1];
                    p1 = __expf((acc[nt][half*2+1] + bias) * SCALEF);
                }
                float h0, l0, h1, l1;
                split2(p0, h0, l0); split2(p1, h1, l1);
                *(float2*)&sm[OFF_PHI + r * QS + mloc] = make_float2(h0, h1);
                *(float2*)&sm[OFF_PLO + r * QS + mloc] = make_float2(l0, l1);
            }
        }
        __syncthreads();

        // ---- PV': O' += p V'  (V' = [V | Iv | Ih | p0 | ones]) ----
        {
            const uint32_t* ph = (const uint32_t*)&sm[OFF_PHI + (R0 + ly) * QS + lx];
            const uint32_t* pl = (const uint32_t*)&sm[OFF_PLO + (R0 + ly) * QS + lx];
            #pragma unroll
            for (int k8 = 0; k8 < 8; k8++) {
                int kc = k8 * 8;
                uint32_t ah0 = ph[kc], ah1 = ph[8*QS + kc], ah2 = ph[kc+4], ah3 = ph[8*QS + kc+4];
                uint32_t al0 = pl[kc], al1 = pl[8*QS + kc], al2 = pl[kc+4], al3 = pl[8*QS + kc+4];
                #pragma unroll
                for (int nt = 0; nt < 4; nt++) {
                    int nb = colblk * 32 + nt * 8;
                    const uint32_t* bh = (const uint32_t*)&sm[OFF_VHI + (kc + lx) * VS + nb + ly];
                    const uint32_t* bl = (const uint32_t*)&sm[OFF_VLO + (kc + lx) * VS + nb + ly];
                    uint32_t bh0 = bh[0], bh1 = bh[4*VS], bl0 = bl[0], bl1 = bl[4*VS];
                    mma_tf32(accO[nt], ah0, ah1, ah2, ah3, bh0, bh1);
                    mma_tf32(accO[nt], al0, al1, al2, al3, bh0, bh1);
                    mma_tf32(accO[nt], ah0, ah1, ah2, ah3, bl0, bl1);
                }
            }
        }
    }

    // ---------------- stage O' to smem (K region is dead) ----------------
    #pragma unroll
    for (int nt = 0; nt < 4; nt++) {
        #pragma unroll
        for (int half = 0; half < 2; half++) {
            int r = R0 + ly + half * 8;
            int col = colblk * 32 + nt * 8 + lx * 2;
            *(float2*)&sm[OFF_PART + r * 128 + col] =
                make_float2(accO[nt][half*2], accO[nt][half*2+1]);
        }
    }
    __syncthreads();

    // ---------------- epilogue: rel-v rank-1 terms from O' cols, normalize, store
    {
        int n  = tid >> 3;
        int d0 = (tid & 7) * 8;
        const float* prow = &sm[OFF_PART + n * 128];
        float o[8];
        #pragma unroll
        for (int dd = 0; dd < 8; dd++) o[dd] = prow[d0 + dd];

        int qn = n0 + n;
        bool zi = (qn == 0) || (qn >= NN);
        int gq = 0, cq = 0;
        if (!zi) { gq = (qn - 1) / 24; cq = (qn - 1) % 24; }

        {   // m=0 term
            float c0 = prow[112];
            float4 a  = __ldg((const float4*)&tvv[d0]);
            float4 a2 = __ldg((const float4*)&tvv[d0 + 4]);
            float4 bb = __ldg((const float4*)&tvh[d0]);
            float4 b2 = __ldg((const float4*)&tvh[d0 + 4]);
            o[0] += c0 * (a.x + bb.x); o[1] += c0 * (a.y + bb.y);
            o[2] += c0 * (a.z + bb.z); o[3] += c0 * (a.w + bb.w);
            o[4] += c0 * (a2.x + b2.x); o[5] += c0 * (a2.y + b2.y);
            o[6] += c0 * (a2.z + b2.z); o[7] += c0 * (a2.w + b2.w);
        }
        #pragma unroll 4
        for (int g = 0; g < 24; g++) {
            int t = zi ? 0 : clip14(g - gq);
            float coef = prow[64 + g];
            const float* tr = &tvv[t * 64 + d0];
            float4 a  = __ldg((const float4*)tr);
            float4 a2 = __ldg((const float4*)(tr + 4));
            o[0] += coef * a.x;  o[1] += coef * a.y;  o[2] += coef * a.z;  o[3] += coef * a.w;
            o[4] += coef * a2.x; o[5] += coef * a2.y; o[6] += coef * a2.z; o[7] += coef * a2.w;
        }
        #pragma unroll 4
        for (int c2 = 0; c2 < 24; c2++) {
            int t = zi ? 0 : clip14(c2 - cq);
            float coef = prow[88 + c2];
            const float* tr = &tvh[t * 64 + d0];
            float4 a  = __ldg((const float4*)tr);
            float4 a2 = __ldg((const float4*)(tr + 4));
            o[0] += coef * a.x;  o[1] += coef * a.y;  o[2] += coef * a.z;  o[3] += coef * a.w;
            o[4] += coef * a2.x; o[5] += coef * a2.y; o[6] += coef * a2.z; o[7] += coef * a2.w;
        }

        float invs = 1.f / prow[113];
        if (qn < NN) {
            float* op = &out[((size_t)(b * NN + qn)) * OS + h * 64 + d0];
            *(float4*)op       = make_float4(o[0] * invs, o[1] * invs, o[2] * invs, o[3] * invs);
            *(float4*)(op + 4) = make_float4(o[4] * invs, o[5] * invs, o[6] * invs, o[7] * invs);
        }
    }
}

extern "C" void kernel_launch(void* const* d_in, const int* in_sizes, int n_in,
                              void* d_out, int out_size) {
    const float* x   = (const float*)d_in[0];
    const float* wts = (const float*)d_in[1];
    const float* tkv = (const float*)d_in[2];
    const float* tkh = (const float*)d_in[3];
    const float* tvv = (const float*)d_in[4];
    const float* tvh = (const float*)d_in[5];
    float* out = (float*)d_out;

    size_t smem = SMEM_FLOATS * sizeof(float);   // 186,624 B
    cudaFuncSetAttribute(attn_kernel, cudaFuncAttributeMaxDynamicSharedMemorySize, (int)smem);
    dim3 grid(10, HH, BB);                       // (ceil(577/64), 12, 16)
    attn_kernel<<<grid, NT, smem>>>(x, wts, tkv, tkh, tvv, tvh, out);
    (void)in_sizes; (void)n_in; (void)out_size;
}